// round 16
// baseline (speedup 1.0000x reference)
#include <cuda_runtime.h>
#include <cuda_fp16.h>
#include <cstdint>
#include <math_constants.h>

#define BB 4
#define TT 2048
#define CC 1024
#define HH 1024

typedef __half fp16;

// ---------------- scratch (static device globals) ---------------------------
__device__ __align__(16) fp16  g_xh [(size_t)BB*TT*CC];
__device__ __align__(16) fp16  g_Wt [(size_t)3*CC*HH];   // [Wq^T;Wk^T;Wv^T]
__device__ __align__(16) fp16  g_Qh [(size_t)BB*TT*HH];
__device__ __align__(16) fp16  g_Kh [(size_t)BB*TT*HH];
__device__ __align__(16) fp16  g_Vt [(size_t)BB*HH*TT];  // V^T per batch
__device__ __align__(16) float g_S  [(size_t)BB*TT*TT];
__device__ __align__(16) fp16  g_P  [(size_t)BB*TT*TT];

// ---------------- PTX helpers ----------------------------------------------
__device__ __forceinline__ uint32_t smem_u32(const void* p) {
    uint32_t a;
    asm("{ .reg .u64 t; cvta.to.shared.u64 t, %1; cvt.u32.u64 %0, t; }"
        : "=r"(a) : "l"(p));
    return a;
}
__device__ __forceinline__ void ldsm4(uint32_t* r, uint32_t addr) {
    asm volatile("ldmatrix.sync.aligned.m8n8.x4.shared.b16 {%0,%1,%2,%3}, [%4];"
                 : "=r"(r[0]), "=r"(r[1]), "=r"(r[2]), "=r"(r[3]) : "r"(addr));
}
__device__ __forceinline__ void mma16816(float* c, const uint32_t* a, const uint32_t* b) {
    asm volatile(
        "mma.sync.aligned.m16n8k16.row.col.f32.f16.f16.f32 "
        "{%0,%1,%2,%3}, {%4,%5,%6,%7}, {%8,%9}, {%0,%1,%2,%3};"
        : "+f"(c[0]), "+f"(c[1]), "+f"(c[2]), "+f"(c[3])
        : "r"(a[0]), "r"(a[1]), "r"(a[2]), "r"(a[3]), "r"(b[0]), "r"(b[1]));
}
__device__ __forceinline__ void cpasync16(uint32_t saddr, const void* g) {
    asm volatile("cp.async.cg.shared.global [%0], [%1], 16;" :: "r"(saddr), "l"(g));
}
#define CP_COMMIT()  asm volatile("cp.async.commit_group;" ::: "memory")
#define CP_WAIT1()   asm volatile("cp.async.wait_group 1;" ::: "memory")

// ---------------- single-pass fp16 tensor-core GEMM -------------------------
// 64x128 CTA tile, BK=32, 3-stage cp.async pipeline, 256 threads (warp grid
// 2Mx4N, 32x32 per warp, ~80 regs -> 3 CTAs/SM = 24 warps). D = A @ B^T.
// MODE 0: fused QKV projections; Q/K fp16 direct, V transposed via SMEM -> Vt.
// MODE 1: QK^T, pair-packed triangular grid (64-row tiles), scale, fp32 S out.
// MODE 2: PV, k-limit (by+1)*64, long rows first, fp32 out.
#define TILE_A_B  5120          // 64 rows * 80 bytes
#define STAGE_SZ  15360
#define SMEMSZ    46080         // 3 stages

template<int MODE>
__global__ void __launch_bounds__(256, 3) mma_gemm(
    const fp16* __restrict__ A, const fp16* __restrict__ B,
    int K, size_t aB, size_t bB,
    float* __restrict__ Cf, size_t cB, int ldc, float scale,
    fp16* __restrict__ Qh, fp16* __restrict__ Kh, fp16* __restrict__ Vt)
{
    extern __shared__ char smem[];
    int bx, by;
    const int bz = blockIdx.z;
    if (MODE == 1) {
        const int i = blockIdx.x;
        int j = (int)((-1.0f + sqrtf(1.0f + 4.0f * (float)i)) * 0.5f);
        while ((j + 1) * (j + 2) <= i) ++j;
        while (j * (j + 1) > i) --j;
        const int r = i - j * (j + 1);
        if (r >= j + 1) { by = 2 * j + 1; bx = r - (j + 1); }
        else            { by = 2 * j;     bx = r; }
    } else if (MODE == 2) {
        bx = blockIdx.x;
        by = gridDim.y - 1 - blockIdx.y;   // long rows first
    } else {
        bx = blockIdx.x;
        by = blockIdx.y;
    }
    int kmax = K;
    if (MODE == 2) { int kl = (by + 1) * 64; kmax = kl < K ? kl : K; }
    const int NC = kmax / 32;

    const int tid  = threadIdx.x;
    const int lane = tid & 31;
    const int warp = tid >> 5;
    const int wm   = warp & 1;     // 2 warps in M -> 32 rows each
    const int wn   = warp >> 1;    // 4 warps in N -> 32 cols each
    const uint32_t sb = smem_u32(smem);

    const fp16* srcA = A + bz * aB + (size_t)by * 64 * K;
    const fp16* srcB = B + bz * bB + (size_t)bx * 128 * K;

    const int lrow = tid >> 2, lcol = tid & 3;  // 64 rows x 4 x 16B
    auto issue = [&](int c) {
        const int k0 = c * 32;
        const uint32_t base = sb + (c % 3) * STAGE_SZ;
        cpasync16(base + lrow * 80 + lcol * 16,
                  srcA + k0 + (size_t)lrow * K + lcol * 8);
        const uint32_t bbase = base + TILE_A_B;
        cpasync16(bbase + lrow * 80 + lcol * 16,
                  srcB + k0 + (size_t)lrow * K + lcol * 8);
        cpasync16(bbase + (lrow + 64) * 80 + lcol * 16,
                  srcB + k0 + (size_t)(lrow + 64) * K + lcol * 8);
    };

    float acc[2][4][4] = {};

    issue(0); CP_COMMIT();
    issue(1); CP_COMMIT();

    for (int c = 0; c < NC; c++) {
        CP_WAIT1();
        __syncthreads();
        if (c + 2 < NC) issue(c + 2);
        CP_COMMIT();

        const uint32_t base = sb + (c % 3) * STAGE_SZ;
        const uint32_t tA = base, tB = base + TILE_A_B;

        #pragma unroll
        for (int k16 = 0; k16 < 2; k16++) {
            uint32_t af[2][4], bf[2][4];
            const int ar   = lane & 15;
            const int aoff = (k16 * 16 + (lane >> 4) * 8) * 2;
            #pragma unroll
            for (int mt = 0; mt < 2; mt++) {
                const uint32_t row = wm * 32 + mt * 16 + ar;
                ldsm4(af[mt], tA + row * 80 + aoff);
            }
            const int br   = (lane & 7) + ((lane >> 4) << 3);
            const int boff = (k16 * 16 + ((lane >> 3) & 1) * 8) * 2;
            #pragma unroll
            for (int np = 0; np < 2; np++) {
                const uint32_t row = wn * 32 + np * 16 + br;
                ldsm4(bf[np], tB + row * 80 + boff);
            }
            #pragma unroll
            for (int mt = 0; mt < 2; mt++)
                #pragma unroll
                for (int nt = 0; nt < 4; nt++)
                    mma16816(acc[mt][nt], af[mt], &bf[nt >> 1][(nt & 1) * 2]);
        }
    }

    // ---------------- epilogue ----------------------------------------------
    const int m0  = by * 64 + wm * 32;
    const int n0g = bx * 128 + wn * 32;
    const bool vblk = (MODE == 0) && (bx >= 16);

    if (!vblk) {
        #pragma unroll
        for (int mt = 0; mt < 2; mt++)
            #pragma unroll
            for (int nt = 0; nt < 4; nt++) {
                const int r  = m0 + mt * 16 + (lane >> 2);
                const float v0 = acc[mt][nt][0], v1 = acc[mt][nt][1];
                const float v2 = acc[mt][nt][2], v3 = acc[mt][nt][3];
                if (MODE == 0) {
                    const int cc  = (n0g & 1023) + nt * 8 + (lane & 3) * 2;
                    const size_t o0 = (size_t)r * HH + cc;
                    const size_t o1 = (size_t)(r + 8) * HH + cc;
                    fp16* dst = (bx >= 8) ? Kh : Qh;
                    *(__half2*)(dst + o0) = __floats2half2_rn(v0, v1);
                    *(__half2*)(dst + o1) = __floats2half2_rn(v2, v3);
                } else {
                    const int cc = n0g + nt * 8 + (lane & 3) * 2;
                    const size_t o0 = bz * cB + (size_t)r * ldc + cc;
                    const size_t o1 = bz * cB + (size_t)(r + 8) * ldc + cc;
                    *(float2*)(Cf + o0) = make_float2(v0 * scale, v1 * scale);
                    *(float2*)(Cf + o1) = make_float2(v2 * scale, v3 * scale);
                }
            }
    } else {
        // V block: transpose 64x128 tile through SMEM, write fp16 Vt[b][H][T]
        __syncthreads();                   // mainloop smem dead
        fp16* hs = (fp16*)smem;            // [128 h][72 t] padded
        #pragma unroll
        for (int mt = 0; mt < 2; mt++)
            #pragma unroll
            for (int nt = 0; nt < 4; nt++) {
                const int r  = wm * 32 + mt * 16 + (lane >> 2);   // token 0..63
                const int cc = wn * 32 + nt * 8 + (lane & 3) * 2; // h 0..127
                hs[cc * 72 + r]           = __float2half(acc[mt][nt][0]);
                hs[(cc + 1) * 72 + r]     = __float2half(acc[mt][nt][1]);
                hs[cc * 72 + r + 8]       = __float2half(acc[mt][nt][2]);
                hs[(cc + 1) * 72 + r + 8] = __float2half(acc[mt][nt][3]);
            }
        __syncthreads();
        const int b     = by >> 5;              // 32 token-tiles per batch
        const int tcol0 = (by & 31) * 64;
        const int hl    = tid >> 1;             // local h row 0..127
        const int ch    = tid & 1;              // 32-half chunk
        const size_t gb = (size_t)b * HH * TT
                        + (size_t)((bx & 7) * 128 + hl) * TT + tcol0 + ch * 32;
        #pragma unroll
        for (int k = 0; k < 4; k++)
            *(uint4*)(Vt + gb + k * 8) = *(const uint4*)&hs[hl * 72 + ch * 32 + k * 8];
    }
}

// ---------------- merged prep, TIGHT 1-D grid -------------------------------
// blocks [0, 4096)           : x fp32->fp16 convert (512 float4 each)
// blocks [4096, 4096+3072)   : weight transpose, 1024 blocks per matrix
__global__ void __launch_bounds__(256) prep_inputs(
    const float* __restrict__ x,
    const float* __restrict__ W0, const float* __restrict__ W1,
    const float* __restrict__ W2,
    fp16* __restrict__ xh, fp16* __restrict__ Wt)
{
    const int blk = blockIdx.x;
    if (blk < 4096) {
        #pragma unroll
        for (int u = 0; u < 2; u++) {
            const int i = (blk * 2 + u) * 256 + threadIdx.x;
            float4 v = ((const float4*)x)[i];
            ((__half2*)xh)[2 * i]     = __floats2half2_rn(v.x, v.y);
            ((__half2*)xh)[2 * i + 1] = __floats2half2_rn(v.z, v.w);
        }
    } else {
        __shared__ float t[32][33];
        const int tb = blk - 4096;          // 0..3071
        const int z  = tb >> 10;            // matrix 0..2
        const int ti = tb & 1023;           // 32x32 tile index
        const float* in = (z == 0) ? W0 : (z == 1) ? W1 : W2;
        fp16* dst = Wt + (size_t)z * CC * HH;
        const int c0 = (ti & 31) * 32, r0 = (ti >> 5) * 32;
        const int tx = threadIdx.x & 31, ty = threadIdx.x >> 5;
        #pragma unroll
        for (int i = 0; i < 4; i++)
            t[ty + 8 * i][tx] = in[(size_t)(r0 + ty + 8 * i) * HH + c0 + tx];
        __syncthreads();
        #pragma unroll
        for (int i = 0; i < 4; i++)
            dst[(size_t)(c0 + ty + 8 * i) * CC + r0 + tx] =
                __float2half(t[tx][ty + 8 * i]);
    }
}

// ---------------- bounded causal softmax (R14 shape): fp32 S -> fp16 P ------
__global__ void __launch_bounds__(256) softmax_p(
    const float* __restrict__ S, fp16* __restrict__ P)
{
    const int t = blockIdx.x;
    const int b = blockIdx.y;
    const size_t rbase = ((size_t)b * TT + t) * TT;
    const float* row = S + rbase;
    const int len   = t + 1;
    const int bound = ((t >> 7) + 1) << 7;   // ceil128(len)
    const int tid = threadIdx.x;
    const int lane = tid & 31;
    const int warp = tid >> 5;

    __shared__ float red[8];

    float4 va[2];
    float mx = -CUDART_INF_F;
    #pragma unroll
    for (int i = 0; i < 2; i++) {
        const int i4 = tid * 4 + i * 1024;
        if (i4 < bound) {
            float4 x = *(const float4*)(row + i4);
            x.x = (i4 + 0 < len) ? x.x : -CUDART_INF_F;
            x.y = (i4 + 1 < len) ? x.y : -CUDART_INF_F;
            x.z = (i4 + 2 < len) ? x.z : -CUDART_INF_F;
            x.w = (i4 + 3 < len) ? x.w : -CUDART_INF_F;
            va[i] = x;
            mx = fmaxf(mx, fmaxf(fmaxf(x.x, x.y), fmaxf(x.z, x.w)));
        } else {
            va[i] = make_float4(-CUDART_INF_F, -CUDART_INF_F, -CUDART_INF_F, -CUDART_INF_F);
        }
    }
    #pragma unroll
    for (int o = 16; o > 0; o >>= 1)
        mx = fmaxf(mx, __shfl_xor_sync(0xffffffffu, mx, o));
    if (lane == 0) red[warp] = mx;
    __syncthreads();
    float bmx = red[lane & 7];
    #pragma unroll
    for (int o = 4; o > 0; o >>= 1)
        bmx = fmaxf(bmx, __shfl_xor_sync(0xffffffffu, bmx, o));
    bmx = __shfl_sync(0xffffffffu, bmx, 0);

    float sum = 0.f;
    #pragma unroll
    for (int i = 0; i < 2; i++) {
        va[i].x = __expf(va[i].x - bmx);
        va[i].y = __expf(va[i].y - bmx);
        va[i].z = __expf(va[i].z - bmx);
        va[i].w = __expf(va[i].w - bmx);
        sum += (va[i].x + va[i].y) + (va[i].z + va[i].w);
    }
    #pragma unroll
    for (int o = 16; o > 0; o >>= 1)
        sum += __shfl_xor_sync(0xffffffffu, sum, o);
    if (lane == 0) red[warp] = sum;
    __syncthreads();
    float bsum = red[lane & 7];
    #pragma unroll
    for (int o = 4; o > 0; o >>= 1)
        bsum = bsum + __shfl_xor_sync(0xffffffffu, bsum, o);
    bsum = __shfl_sync(0xffffffffu, bsum, 0);

    const float inv = 1.0f / bsum;
    #pragma unroll
    for (int i = 0; i < 2; i++) {
        const int i4 = tid * 4 + i * 1024;
        if (i4 < bound) {
            *(__half2*)(P + rbase + i4)     = __floats2half2_rn(va[i].x * inv, va[i].y * inv);
            *(__half2*)(P + rbase + i4 + 2) = __floats2half2_rn(va[i].z * inv, va[i].w * inv);
        }
    }
}

// ---------------------------------------------------------------------------
extern "C" void kernel_launch(void* const* d_in, const int* in_sizes, int n_in,
                              void* d_out, int out_size)
{
    int xi = 0;
    for (int i = 0; i < n_in; i++)
        if (in_sizes[i] == BB * TT * CC) { xi = i; break; }
    const float* x = (const float*)d_in[xi];
    const float* w[3];
    int wi = 0;
    for (int i = 0; i < n_in && wi < 3; i++)
        if (i != xi) w[wi++] = (const float*)d_in[i];
    const float* Wk = w[0];
    const float* Wq = w[1];
    const float* Wv = w[2];
    float* out = (float*)d_out;

    fp16 *xh, *Wt, *Qh, *Kh, *Vt, *P;
    float *S;
    cudaGetSymbolAddress((void**)&xh, g_xh);
    cudaGetSymbolAddress((void**)&Wt, g_Wt);
    cudaGetSymbolAddress((void**)&Qh, g_Qh);
    cudaGetSymbolAddress((void**)&Kh, g_Kh);
    cudaGetSymbolAddress((void**)&Vt, g_Vt);
    cudaGetSymbolAddress((void**)&S,  g_S);
    cudaGetSymbolAddress((void**)&P,  g_P);

    cudaFuncSetAttribute(mma_gemm<0>, cudaFuncAttributeMaxDynamicSharedMemorySize, SMEMSZ);
    cudaFuncSetAttribute(mma_gemm<1>, cudaFuncAttributeMaxDynamicSharedMemorySize, SMEMSZ);
    cudaFuncSetAttribute(mma_gemm<2>, cudaFuncAttributeMaxDynamicSharedMemorySize, SMEMSZ);

    const float scale = 1.0f / 32.0f;

    // tight merged prep: 4096 conv blocks + 3072 transpose blocks
    prep_inputs<<<4096 + 3072, 256>>>(x, Wq, Wk, Wv, xh, Wt);

    // fused projections: [8192,1024] x [1024,3072]; V transposed in epilogue
    dim3 gp(3 * HH / 128, BB * TT / 64, 1);
    mma_gemm<0><<<gp, 256, SMEMSZ>>>(xh, Wt, CC, 0, 0,
                                     nullptr, 0, 0, 1.f, Qh, Kh, Vt);

    // S = scale * Q K^T, pair-packed triangular grid (64-row x 128-col tiles)
    const int npair = TT / 128;                  // 16 pairs
    dim3 gs(npair * (npair + 1), 1, BB);         // 272 tiles per batch
    mma_gemm<1><<<gs, 256, SMEMSZ>>>(Qh, Kh, HH,
                                     (size_t)TT * HH, (size_t)TT * HH,
                                     S, (size_t)TT * TT, TT, scale,
                                     nullptr, nullptr, nullptr);

    // softmax: 1 row per block (measured-best R14 shape)
    softmax_p<<<dim3(TT, BB), 256>>>(S, P);

    // O = P V, causal k-limit, long rows first
    dim3 gpv(HH / 128, TT / 64, BB);
    mma_gemm<2><<<gpv, 256, SMEMSZ>>>(P, Vt, TT,
                                      (size_t)TT * TT, (size_t)HH * TT,
                                      out, (size_t)TT * HH, HH, 1.f,
                                      nullptr, nullptr, nullptr);
}

// round 17
// speedup vs baseline: 1.0076x; 1.0076x over previous
#include <cuda_runtime.h>
#include <cuda_fp16.h>
#include <cstdint>
#include <math_constants.h>

#define BB 4
#define TT 2048
#define CC 1024
#define HH 1024

typedef __half fp16;

// ---------------- scratch (static device globals) ---------------------------
__device__ __align__(16) fp16  g_xh [(size_t)BB*TT*CC];
__device__ __align__(16) fp16  g_Wt [(size_t)3*CC*HH];   // [Wq^T;Wk^T;Wv^T]
__device__ __align__(16) fp16  g_Qh [(size_t)BB*TT*HH];
__device__ __align__(16) fp16  g_Kh [(size_t)BB*TT*HH];
__device__ __align__(16) fp16  g_Vt [(size_t)BB*HH*TT];  // V^T per batch
__device__ __align__(16) fp16  g_Sh [(size_t)BB*TT*TT];  // fp16 logits
__device__ __align__(16) fp16  g_P  [(size_t)BB*TT*TT];

// ---------------- PTX helpers ----------------------------------------------
__device__ __forceinline__ uint32_t smem_u32(const void* p) {
    uint32_t a;
    asm("{ .reg .u64 t; cvta.to.shared.u64 t, %1; cvt.u32.u64 %0, t; }"
        : "=r"(a) : "l"(p));
    return a;
}
__device__ __forceinline__ void ldsm4(uint32_t* r, uint32_t addr) {
    asm volatile("ldmatrix.sync.aligned.m8n8.x4.shared.b16 {%0,%1,%2,%3}, [%4];"
                 : "=r"(r[0]), "=r"(r[1]), "=r"(r[2]), "=r"(r[3]) : "r"(addr));
}
__device__ __forceinline__ void mma16816(float* c, const uint32_t* a, const uint32_t* b) {
    asm volatile(
        "mma.sync.aligned.m16n8k16.row.col.f32.f16.f16.f32 "
        "{%0,%1,%2,%3}, {%4,%5,%6,%7}, {%8,%9}, {%0,%1,%2,%3};"
        : "+f"(c[0]), "+f"(c[1]), "+f"(c[2]), "+f"(c[3])
        : "r"(a[0]), "r"(a[1]), "r"(a[2]), "r"(a[3]), "r"(b[0]), "r"(b[1]));
}
__device__ __forceinline__ void cpasync16(uint32_t saddr, const void* g) {
    asm volatile("cp.async.cg.shared.global [%0], [%1], 16;" :: "r"(saddr), "l"(g));
}
#define CP_COMMIT()  asm volatile("cp.async.commit_group;" ::: "memory")
#define CP_WAIT1()   asm volatile("cp.async.wait_group 1;" ::: "memory")

// ---------------- single-pass fp16 tensor-core GEMM -------------------------
// 64x128 CTA tile, BK=32, 3-stage cp.async pipeline, 256 threads (warp grid
// 2Mx4N, 32x32 per warp, ~80 regs -> 3 CTAs/SM = 24 warps). D = A @ B^T.
// MODE 0: fused QKV projections; Q/K fp16 direct, V transposed via SMEM -> Vt.
// MODE 1: QK^T, pair-packed triangular grid, scale, fp16 S out.
// MODE 2: PV, k-limit (by+1)*64, long rows first, fp32 out.
#define TILE_A_B  5120          // 64 rows * 80 bytes
#define STAGE_SZ  15360
#define SMEMSZ    46080         // 3 stages

template<int MODE>
__global__ void __launch_bounds__(256, 3) mma_gemm(
    const fp16* __restrict__ A, const fp16* __restrict__ B,
    int K, size_t aB, size_t bB,
    float* __restrict__ Cf, fp16* __restrict__ Ch, size_t cB, int ldc, float scale,
    fp16* __restrict__ Qh, fp16* __restrict__ Kh, fp16* __restrict__ Vt)
{
    extern __shared__ char smem[];
    int bx, by;
    const int bz = blockIdx.z;
    if (MODE == 1) {
        const int i = blockIdx.x;
        int j = (int)((-1.0f + sqrtf(1.0f + 4.0f * (float)i)) * 0.5f);
        while ((j + 1) * (j + 2) <= i) ++j;
        while (j * (j + 1) > i) --j;
        const int r = i - j * (j + 1);
        if (r >= j + 1) { by = 2 * j + 1; bx = r - (j + 1); }
        else            { by = 2 * j;     bx = r; }
    } else if (MODE == 2) {
        bx = blockIdx.x;
        by = gridDim.y - 1 - blockIdx.y;   // long rows first
    } else {
        bx = blockIdx.x;
        by = blockIdx.y;
    }
    int kmax = K;
    if (MODE == 2) { int kl = (by + 1) * 64; kmax = kl < K ? kl : K; }
    const int NC = kmax / 32;

    const int tid  = threadIdx.x;
    const int lane = tid & 31;
    const int warp = tid >> 5;
    const int wm   = warp & 1;     // 2 warps in M -> 32 rows each
    const int wn   = warp >> 1;    // 4 warps in N -> 32 cols each
    const uint32_t sb = smem_u32(smem);

    const fp16* srcA = A + bz * aB + (size_t)by * 64 * K;
    const fp16* srcB = B + bz * bB + (size_t)bx * 128 * K;

    const int lrow = tid >> 2, lcol = tid & 3;  // 64 rows x 4 x 16B
    auto issue = [&](int c) {
        const int k0 = c * 32;
        const uint32_t base = sb + (c % 3) * STAGE_SZ;
        cpasync16(base + lrow * 80 + lcol * 16,
                  srcA + k0 + (size_t)lrow * K + lcol * 8);
        const uint32_t bbase = base + TILE_A_B;
        cpasync16(bbase + lrow * 80 + lcol * 16,
                  srcB + k0 + (size_t)lrow * K + lcol * 8);
        cpasync16(bbase + (lrow + 64) * 80 + lcol * 16,
                  srcB + k0 + (size_t)(lrow + 64) * K + lcol * 8);
    };

    float acc[2][4][4] = {};

    issue(0); CP_COMMIT();
    issue(1); CP_COMMIT();

    for (int c = 0; c < NC; c++) {
        CP_WAIT1();
        __syncthreads();
        if (c + 2 < NC) issue(c + 2);
        CP_COMMIT();

        const uint32_t base = sb + (c % 3) * STAGE_SZ;
        const uint32_t tA = base, tB = base + TILE_A_B;

        #pragma unroll
        for (int k16 = 0; k16 < 2; k16++) {
            uint32_t af[2][4], bf[2][4];
            const int ar   = lane & 15;
            const int aoff = (k16 * 16 + (lane >> 4) * 8) * 2;
            #pragma unroll
            for (int mt = 0; mt < 2; mt++) {
                const uint32_t row = wm * 32 + mt * 16 + ar;
                ldsm4(af[mt], tA + row * 80 + aoff);
            }
            const int br   = (lane & 7) + ((lane >> 4) << 3);
            const int boff = (k16 * 16 + ((lane >> 3) & 1) * 8) * 2;
            #pragma unroll
            for (int np = 0; np < 2; np++) {
                const uint32_t row = wn * 32 + np * 16 + br;
                ldsm4(bf[np], tB + row * 80 + boff);
            }
            #pragma unroll
            for (int mt = 0; mt < 2; mt++)
                #pragma unroll
                for (int nt = 0; nt < 4; nt++)
                    mma16816(acc[mt][nt], af[mt], &bf[nt >> 1][(nt & 1) * 2]);
        }
    }

    // ---------------- epilogue ----------------------------------------------
    const int m0  = by * 64 + wm * 32;
    const int n0g = bx * 128 + wn * 32;
    const bool vblk = (MODE == 0) && (bx >= 16);

    if (!vblk) {
        #pragma unroll
        for (int mt = 0; mt < 2; mt++)
            #pragma unroll
            for (int nt = 0; nt < 4; nt++) {
                const int r  = m0 + mt * 16 + (lane >> 2);
                const float v0 = acc[mt][nt][0], v1 = acc[mt][nt][1];
                const float v2 = acc[mt][nt][2], v3 = acc[mt][nt][3];
                if (MODE == 0) {
                    const int cc  = (n0g & 1023) + nt * 8 + (lane & 3) * 2;
                    const size_t o0 = (size_t)r * HH + cc;
                    const size_t o1 = (size_t)(r + 8) * HH + cc;
                    fp16* dst = (bx >= 8) ? Kh : Qh;
                    *(__half2*)(dst + o0) = __floats2half2_rn(v0, v1);
                    *(__half2*)(dst + o1) = __floats2half2_rn(v2, v3);
                } else if (MODE == 1) {
                    const int cc = n0g + nt * 8 + (lane & 3) * 2;
                    const size_t o0 = bz * cB + (size_t)r * ldc + cc;
                    const size_t o1 = bz * cB + (size_t)(r + 8) * ldc + cc;
                    *(__half2*)(Ch + o0) = __floats2half2_rn(v0 * scale, v1 * scale);
                    *(__half2*)(Ch + o1) = __floats2half2_rn(v2 * scale, v3 * scale);
                } else {
                    const int cc = n0g + nt * 8 + (lane & 3) * 2;
                    const size_t o0 = bz * cB + (size_t)r * ldc + cc;
                    const size_t o1 = bz * cB + (size_t)(r + 8) * ldc + cc;
                    *(float2*)(Cf + o0) = make_float2(v0, v1);
                    *(float2*)(Cf + o1) = make_float2(v2, v3);
                }
            }
    } else {
        // V block: transpose 64x128 tile through SMEM, write fp16 Vt[b][H][T]
        __syncthreads();                   // mainloop smem dead
        fp16* hs = (fp16*)smem;            // [128 h][72 t] padded
        #pragma unroll
        for (int mt = 0; mt < 2; mt++)
            #pragma unroll
            for (int nt = 0; nt < 4; nt++) {
                const int r  = wm * 32 + mt * 16 + (lane >> 2);   // token 0..63
                const int cc = wn * 32 + nt * 8 + (lane & 3) * 2; // h 0..127
                hs[cc * 72 + r]           = __float2half(acc[mt][nt][0]);
                hs[(cc + 1) * 72 + r]     = __float2half(acc[mt][nt][1]);
                hs[cc * 72 + r + 8]       = __float2half(acc[mt][nt][2]);
                hs[(cc + 1) * 72 + r + 8] = __float2half(acc[mt][nt][3]);
            }
        __syncthreads();
        const int b     = by >> 5;              // 32 token-tiles per batch
        const int tcol0 = (by & 31) * 64;
        const int hl    = tid >> 1;             // local h row 0..127
        const int ch    = tid & 1;              // 32-half chunk
        const size_t gb = (size_t)b * HH * TT
                        + (size_t)((bx & 7) * 128 + hl) * TT + tcol0 + ch * 32;
        #pragma unroll
        for (int k = 0; k < 4; k++)
            *(uint4*)(Vt + gb + k * 8) = *(const uint4*)&hs[hl * 72 + ch * 32 + k * 8];
    }
}

// ---------------- merged prep, TIGHT 1-D grid -------------------------------
// blocks [0, 4096)           : x fp32->fp16 convert (512 float4 each)
// blocks [4096, 4096+3072)   : weight transpose, 1024 blocks per matrix
__global__ void __launch_bounds__(256) prep_inputs(
    const float* __restrict__ x,
    const float* __restrict__ W0, const float* __restrict__ W1,
    const float* __restrict__ W2,
    fp16* __restrict__ xh, fp16* __restrict__ Wt)
{
    const int blk = blockIdx.x;
    if (blk < 4096) {
        #pragma unroll
        for (int u = 0; u < 2; u++) {
            const int i = (blk * 2 + u) * 256 + threadIdx.x;
            float4 v = ((const float4*)x)[i];
            ((__half2*)xh)[2 * i]     = __floats2half2_rn(v.x, v.y);
            ((__half2*)xh)[2 * i + 1] = __floats2half2_rn(v.z, v.w);
        }
    } else {
        __shared__ float t[32][33];
        const int tb = blk - 4096;          // 0..3071
        const int z  = tb >> 10;            // matrix 0..2
        const int ti = tb & 1023;           // 32x32 tile index
        const float* in = (z == 0) ? W0 : (z == 1) ? W1 : W2;
        fp16* dst = Wt + (size_t)z * CC * HH;
        const int c0 = (ti & 31) * 32, r0 = (ti >> 5) * 32;
        const int tx = threadIdx.x & 31, ty = threadIdx.x >> 5;
        #pragma unroll
        for (int i = 0; i < 4; i++)
            t[ty + 8 * i][tx] = in[(size_t)(r0 + ty + 8 * i) * HH + c0 + tx];
        __syncthreads();
        #pragma unroll
        for (int i = 0; i < 4; i++)
            dst[(size_t)(c0 + ty + 8 * i) * CC + r0 + tx] =
                __float2half(t[tx][ty + 8 * i]);
    }
}

// ---------------- bounded causal softmax: fp16 S -> fp16 P ------------------
// One row per block, 256 threads; each thread owns 8 contiguous halves
// (one uint4 load + one uint4 store). 256*8 = 2048 = full row.
__global__ void __launch_bounds__(256) softmax_p(
    const fp16* __restrict__ Sh, fp16* __restrict__ P)
{
    const int t = blockIdx.x;
    const int b = blockIdx.y;
    const size_t rbase = ((size_t)b * TT + t) * TT;
    const int len   = t + 1;
    const int bound = ((t >> 7) + 1) << 7;   // ceil128(len)
    const int tid = threadIdx.x;
    const int lane = tid & 31;
    const int warp = tid >> 5;
    const int i8  = tid * 8;
    const bool act = (i8 < bound);

    __shared__ float red[8];

    float v[8];
    float mx = -CUDART_INF_F;
    if (act) {
        uint4 raw = *(const uint4*)(Sh + rbase + i8);
        const __half2* h2 = (const __half2*)&raw;
        #pragma unroll
        for (int q = 0; q < 4; q++) {
            float2 f = __half22float2(h2[q]);
            v[2 * q]     = (i8 + 2 * q     < len) ? f.x : -CUDART_INF_F;
            v[2 * q + 1] = (i8 + 2 * q + 1 < len) ? f.y : -CUDART_INF_F;
        }
        #pragma unroll
        for (int q = 0; q < 8; q++) mx = fmaxf(mx, v[q]);
    }
    #pragma unroll
    for (int o = 16; o > 0; o >>= 1)
        mx = fmaxf(mx, __shfl_xor_sync(0xffffffffu, mx, o));
    if (lane == 0) red[warp] = mx;
    __syncthreads();
    float bmx = red[lane & 7];
    #pragma unroll
    for (int o = 4; o > 0; o >>= 1)
        bmx = fmaxf(bmx, __shfl_xor_sync(0xffffffffu, bmx, o));
    bmx = __shfl_sync(0xffffffffu, bmx, 0);

    float sum = 0.f;
    if (act) {
        #pragma unroll
        for (int q = 0; q < 8; q++) {
            v[q] = __expf(v[q] - bmx);
            sum += v[q];
        }
    }
    #pragma unroll
    for (int o = 16; o > 0; o >>= 1)
        sum += __shfl_xor_sync(0xffffffffu, sum, o);
    if (lane == 0) red[warp] = sum;
    __syncthreads();
    float bsum = red[lane & 7];
    #pragma unroll
    for (int o = 4; o > 0; o >>= 1)
        bsum = bsum + __shfl_xor_sync(0xffffffffu, bsum, o);
    bsum = __shfl_sync(0xffffffffu, bsum, 0);

    if (act) {
        const float inv = 1.0f / bsum;
        uint4 outw;
        __half2* o2 = (__half2*)&outw;
        #pragma unroll
        for (int q = 0; q < 4; q++)
            o2[q] = __floats2half2_rn(v[2 * q] * inv, v[2 * q + 1] * inv);
        *(uint4*)(P + rbase + i8) = outw;
    }
}

// ---------------------------------------------------------------------------
extern "C" void kernel_launch(void* const* d_in, const int* in_sizes, int n_in,
                              void* d_out, int out_size)
{
    int xi = 0;
    for (int i = 0; i < n_in; i++)
        if (in_sizes[i] == BB * TT * CC) { xi = i; break; }
    const float* x = (const float*)d_in[xi];
    const float* w[3];
    int wi = 0;
    for (int i = 0; i < n_in && wi < 3; i++)
        if (i != xi) w[wi++] = (const float*)d_in[i];
    const float* Wk = w[0];
    const float* Wq = w[1];
    const float* Wv = w[2];
    float* out = (float*)d_out;

    fp16 *xh, *Wt, *Qh, *Kh, *Vt, *Sh, *P;
    cudaGetSymbolAddress((void**)&xh, g_xh);
    cudaGetSymbolAddress((void**)&Wt, g_Wt);
    cudaGetSymbolAddress((void**)&Qh, g_Qh);
    cudaGetSymbolAddress((void**)&Kh, g_Kh);
    cudaGetSymbolAddress((void**)&Vt, g_Vt);
    cudaGetSymbolAddress((void**)&Sh, g_Sh);
    cudaGetSymbolAddress((void**)&P,  g_P);

    cudaFuncSetAttribute(mma_gemm<0>, cudaFuncAttributeMaxDynamicSharedMemorySize, SMEMSZ);
    cudaFuncSetAttribute(mma_gemm<1>, cudaFuncAttributeMaxDynamicSharedMemorySize, SMEMSZ);
    cudaFuncSetAttribute(mma_gemm<2>, cudaFuncAttributeMaxDynamicSharedMemorySize, SMEMSZ);

    const float scale = 1.0f / 32.0f;

    // tight merged prep: 4096 conv blocks + 3072 transpose blocks
    prep_inputs<<<4096 + 3072, 256>>>(x, Wq, Wk, Wv, xh, Wt);

    // fused projections: [8192,1024] x [1024,3072]; V transposed in epilogue
    dim3 gp(3 * HH / 128, BB * TT / 64, 1);
    mma_gemm<0><<<gp, 256, SMEMSZ>>>(xh, Wt, CC, 0, 0,
                                     nullptr, nullptr, 0, 0, 1.f, Qh, Kh, Vt);

    // S = scale * Q K^T, pair-packed triangular grid, fp16 out
    const int npair = TT / 128;                  // 16 pairs
    dim3 gs(npair * (npair + 1), 1, BB);         // 272 tiles per batch
    mma_gemm<1><<<gs, 256, SMEMSZ>>>(Qh, Kh, HH,
                                     (size_t)TT * HH, (size_t)TT * HH,
                                     nullptr, Sh, (size_t)TT * TT, TT, scale,
                                     nullptr, nullptr, nullptr);

    // softmax: 1 row per block, fp16 in/out
    softmax_p<<<dim3(TT, BB), 256>>>(Sh, P);

    // O = P V, causal k-limit, long rows first
    dim3 gpv(HH / 128, TT / 64, BB);
    mma_gemm<2><<<gpv, 256, SMEMSZ>>>(P, Vt, TT,
                                      (size_t)TT * TT, (size_t)HH * TT,
                                      out, nullptr, (size_t)TT * HH, HH, 1.f,
                                      nullptr, nullptr, nullptr);
}